// round 5
// baseline (speedup 1.0000x reference)
#include <cuda_runtime.h>
#include <math.h>

#define N_NODES 50000
#define N_EDGES 500000
#define E2 (N_EDGES + N_NODES)   // edges + self loops
#define IN_DIM 128
#define F1 256
#define HH1 4
#define CC1 64
#define F2 64
#define HH2 1
#define CC2 64
#define NBLK_N 196               // ceil(50000/256)

// ---------------- scratch (static device globals; no allocation) ----------------
__device__ float g_h1[(size_t)N_NODES * F1];
__device__ float g_out1[(size_t)N_NODES * F1];
__device__ float g_h2[(size_t)N_NODES * F2];
__device__ float g_ssrc1[N_NODES * HH1];
__device__ float g_sdst1[N_NODES * HH1];
__device__ float g_ssrc2[N_NODES * HH2];
__device__ float g_sdst2[N_NODES * HH2];
__device__ float g_asum[N_NODES];
__device__ int   g_deg[N_NODES];
__device__ int   g_part[N_NODES];
__device__ int   g_bsum[256];
__device__ int   g_off[N_NODES + 1];
__device__ int   g_fill[N_NODES];
__device__ int   g_csrc[E2];
__device__ float g_cea[E2];
__device__ float g_ce1[HH1];
__device__ float g_ce2[HH2];

// ---------------- pre: degree + edge-attr stats ----------------
__global__ void init_pre(int* deg, float* asum) {
    int i = blockIdx.x * blockDim.x + threadIdx.x;
    if (i < N_NODES) { deg[i] = 0; asum[i] = 0.f; }
}

__global__ void edge_stats(const int* __restrict__ ei, const float* __restrict__ ea,
                           int* __restrict__ deg, float* __restrict__ asum) {
    int j = blockIdx.x * blockDim.x + threadIdx.x;
    if (j >= N_EDGES) return;
    int d = ei[N_EDGES + j];
    atomicAdd(&deg[d], 1);
    atomicAdd(&asum[d], ea[j]);
}

// ---------------- 3-kernel exclusive scan of (deg+1) -> CSR offsets ----------------
__global__ void scan_block(const int* __restrict__ deg, int* __restrict__ part,
                           int* __restrict__ bsum) {
    __shared__ int sh[256];
    int i = blockIdx.x * 256 + threadIdx.x;
    int v = (i < N_NODES) ? deg[i] + 1 : 0;
    sh[threadIdx.x] = v;
    __syncthreads();
    for (int o = 1; o < 256; o <<= 1) {
        int t = (threadIdx.x >= o) ? sh[threadIdx.x - o] : 0;
        __syncthreads();
        sh[threadIdx.x] += t;
        __syncthreads();
    }
    if (i < N_NODES) part[i] = sh[threadIdx.x] - v;   // exclusive within block
    if (threadIdx.x == 255) bsum[blockIdx.x] = sh[255];
}

__global__ void scan_tops(int* bsum) {  // 1 block; NBLK_N <= 256
    __shared__ int sh[256];
    int v = (threadIdx.x < NBLK_N) ? bsum[threadIdx.x] : 0;
    sh[threadIdx.x] = v;
    __syncthreads();
    for (int o = 1; o < 256; o <<= 1) {
        int t = (threadIdx.x >= o) ? sh[threadIdx.x - o] : 0;
        __syncthreads();
        sh[threadIdx.x] += t;
        __syncthreads();
    }
    if (threadIdx.x < NBLK_N) bsum[threadIdx.x] = sh[threadIdx.x] - v;  // exclusive
}

// offsets + self-loop (slot 0) + loop-attr, fused
__global__ void scan_final_selfloop(const int* __restrict__ part, const int* __restrict__ bsum,
                                    const int* __restrict__ deg, const float* __restrict__ asum,
                                    int* __restrict__ off, int* __restrict__ csrc,
                                    float* __restrict__ cea, int* __restrict__ fill) {
    int i = blockIdx.x * 256 + threadIdx.x;
    if (i < N_NODES) {
        int o = part[i] + bsum[blockIdx.x];
        off[i] = o;
        csrc[o] = i;
        cea[o] = asum[i] / fmaxf((float)deg[i], 1.f);
        fill[i] = 1;
    }
    if (i == 0) off[N_NODES] = E2;
}

__global__ void csr_fill(const int* __restrict__ ei, const float* __restrict__ ea,
                         const int* __restrict__ off, int* __restrict__ fill,
                         int* __restrict__ csrc, float* __restrict__ cea) {
    int j = blockIdx.x * blockDim.x + threadIdx.x;
    if (j >= N_EDGES) return;
    int d = ei[N_EDGES + j];
    int p = off[d] + atomicAdd(&fill[d], 1);
    csrc[p] = ei[j];
    cea[p] = ea[j];
}

// ---------------- GEMM + fused attention-score epilogue ----------------
// C[M,NC] = A[M,K] @ B[K,NC]; BM=128, BK=32, TM=8; also writes
// ssrc[row,h] = sum_c C[row, h*64+c] * a_src[h*64+c], sdst likewise.
template <int K, int NC, int BN, int TN, int H>
__global__ __launch_bounds__(256) void gemm_score_kernel(
    const float* __restrict__ A, const float* __restrict__ B, float* __restrict__ C,
    const float* __restrict__ a_src, const float* __restrict__ a_dst,
    float* __restrict__ ssrc, float* __restrict__ sdst) {
    const int BM = 128, BK = 32, TM = 8;
    const int TX = BN / TN;                 // 16
    const int nA = (BM * BK / 4) / 256;     // 4
    const int nB = (BK * BN / 4) / 256;     // 4 (BN=128) or 2 (BN=64)
    __shared__ float As[BK][BM + 4];
    __shared__ float Bs[BK][BN];

    const int tid = threadIdx.x;
    const int tx = tid % TX, ty = tid / TX;
    const int mbase = blockIdx.x * BM, cbase = blockIdx.y * BN;
    const int lane = tid & 31;

    float acc[TM][TN] = {};
    float4 rA[nA], rB[nB];

    // prefetch tile 0 into registers
    #pragma unroll
    for (int r = 0; r < nA; r++) {
        int f = tid + r * 256;
        int row = f >> 3, kq = f & 7;
        int gm = mbase + row;
        rA[r] = (gm < N_NODES) ? *(const float4*)(A + (size_t)gm * K + kq * 4)
                               : make_float4(0.f, 0.f, 0.f, 0.f);
    }
    #pragma unroll
    for (int r = 0; r < nB; r++) {
        int f = tid + r * 256;
        int c4 = f % (BN / 4), kr = f / (BN / 4);
        rB[r] = *(const float4*)(B + (size_t)kr * NC + cbase + c4 * 4);
    }

    #pragma unroll
    for (int t = 0; t < K / BK; t++) {
        // stage current tile from registers
        #pragma unroll
        for (int r = 0; r < nA; r++) {
            int f = tid + r * 256;
            int row = f >> 3, kq = f & 7;
            As[kq * 4 + 0][row] = rA[r].x;
            As[kq * 4 + 1][row] = rA[r].y;
            As[kq * 4 + 2][row] = rA[r].z;
            As[kq * 4 + 3][row] = rA[r].w;
        }
        #pragma unroll
        for (int r = 0; r < nB; r++) {
            int f = tid + r * 256;
            int c4 = f % (BN / 4), kr = f / (BN / 4);
            *(float4*)&Bs[kr][c4 * 4] = rB[r];
        }
        __syncthreads();

        // prefetch next tile while computing
        if (t + 1 < K / BK) {
            int kc = (t + 1) * BK;
            #pragma unroll
            for (int r = 0; r < nA; r++) {
                int f = tid + r * 256;
                int row = f >> 3, kq = f & 7;
                int gm = mbase + row;
                rA[r] = (gm < N_NODES) ? *(const float4*)(A + (size_t)gm * K + kc + kq * 4)
                                       : make_float4(0.f, 0.f, 0.f, 0.f);
            }
            #pragma unroll
            for (int r = 0; r < nB; r++) {
                int f = tid + r * 256;
                int c4 = f % (BN / 4), kr = f / (BN / 4);
                rB[r] = *(const float4*)(B + (size_t)(kc + kr) * NC + cbase + c4 * 4);
            }
        }

        #pragma unroll
        for (int k = 0; k < BK; k++) {
            float a[TM], b[TN];
            #pragma unroll
            for (int i = 0; i < TM; i += 4) *(float4*)&a[i] = *(const float4*)&As[k][ty * TM + i];
            #pragma unroll
            for (int j = 0; j < TN; j += 4) *(float4*)&b[j] = *(const float4*)&Bs[k][tx * TN + j];
            #pragma unroll
            for (int i = 0; i < TM; i++)
                #pragma unroll
                for (int j = 0; j < TN; j++) acc[i][j] += a[i] * b[j];
        }
        __syncthreads();
    }

    // store C tile
    #pragma unroll
    for (int i = 0; i < TM; i++) {
        int gm = mbase + ty * TM + i;
        if (gm < N_NODES) {
            #pragma unroll
            for (int j = 0; j < TN; j += 4)
                *(float4*)(C + (size_t)gm * NC + cbase + tx * TN + j) =
                    make_float4(acc[i][j], acc[i][j + 1], acc[i][j + 2], acc[i][j + 3]);
        }
    }

    // fused score epilogue: TPH lanes share one (row, head)
    const int CPH = 64;                 // channels per head
    const int TPH = CPH / TN;           // 8 (BN=128) or 16 (BN=64)
    float av[TN], dv[TN];
    #pragma unroll
    for (int j = 0; j < TN; j++) {
        av[j] = __ldg(a_src + cbase + tx * TN + j);
        dv[j] = __ldg(a_dst + cbase + tx * TN + j);
    }
    const int head = (cbase + tx * TN) / CPH;
    #pragma unroll
    for (int i = 0; i < TM; i++) {
        float ps = 0.f, pd = 0.f;
        #pragma unroll
        for (int j = 0; j < TN; j++) { ps += acc[i][j] * av[j]; pd += acc[i][j] * dv[j]; }
        #pragma unroll
        for (int o = 1; o < TPH; o <<= 1) {
            ps += __shfl_xor_sync(0xFFFFFFFFu, ps, o);
            pd += __shfl_xor_sync(0xFFFFFFFFu, pd, o);
        }
        int gm = mbase + ty * TM + i;
        if ((lane % TPH) == 0 && gm < N_NODES) {
            ssrc[(size_t)gm * H + head] = ps;
            sdst[(size_t)gm * H + head] = pd;
        }
    }
}

// ---------------- ce[h] = dot(We[h*C..], ae[h*C..]) ----------------
template <int H, int C>
__global__ void ce_kernel(const float* __restrict__ We, const float* __restrict__ ae,
                          float* __restrict__ ce) {
    int h = threadIdx.x >> 5;
    int lane = threadIdx.x & 31;
    float s = 0.f;
    for (int c = lane; c < C; c += 32) s += We[h * C + c] * ae[h * C + c];
    #pragma unroll
    for (int off = 16; off > 0; off >>= 1) s += __shfl_xor_sync(0xFFFFFFFFu, s, off);
    if (lane == 0) ce[h] = s;
}

// ---------------- fused online-softmax aggregation: warp per (node, head) ----------------
template <int H, int C, bool ELU>
__global__ __launch_bounds__(256) void node_agg(
    const int* __restrict__ off, const int* __restrict__ csrc, const float* __restrict__ cea,
    const float* __restrict__ ssrc, const float* __restrict__ sdst, const float* __restrict__ ce,
    const float* __restrict__ hfeat, const float* __restrict__ bias, float* __restrict__ out) {
    const int F = H * C;
    int gw = (blockIdx.x * blockDim.x + threadIdx.x) >> 5;
    int lane = threadIdx.x & 31;
    int d = gw / H;
    int h = gw % H;
    if (d >= N_NODES) return;

    const int e0 = off[d], e1 = off[d + 1];
    const float sd = sdst[(size_t)d * H + h];
    const float cv = ce[h];
    const int hoff = h * C + lane * 2;

    float m = -1e30f;     // running max (warp-uniform)
    float ssl = 0.f;      // per-lane partial denom
    float a0 = 0.f, a1 = 0.f;

    for (int base = e0; base < e1; base += 32) {
        int e = base + lane;
        bool valid = e < e1;
        int s = valid ? csrc[e] : 0;
        float v = -1e30f;
        if (valid) {
            float a = cea[e];
            v = ssrc[(size_t)s * H + h] + sd + a * cv;
            v = (v >= 0.f) ? v : 0.2f * v;
        }
        // chunk max -> update running max, rescale accumulators
        float cm = v;
        #pragma unroll
        for (int o = 16; o > 0; o >>= 1) cm = fmaxf(cm, __shfl_xor_sync(0xFFFFFFFFu, cm, o));
        float nm = fmaxf(m, cm);
        float f = __expf(m - nm);
        ssl *= f; a0 *= f; a1 *= f;
        m = nm;
        float w = valid ? __expf(v - m) : 0.f;
        ssl += w;

        // accumulate: shuffle (s, w) per edge; 4-way unrolled gathers
        int n = min(32, e1 - base);
        int k = 0;
        for (; k + 4 <= n; k += 4) {
            int s0 = __shfl_sync(0xFFFFFFFFu, s, k + 0);
            int s1 = __shfl_sync(0xFFFFFFFFu, s, k + 1);
            int s2 = __shfl_sync(0xFFFFFFFFu, s, k + 2);
            int s3 = __shfl_sync(0xFFFFFFFFu, s, k + 3);
            float w0 = __shfl_sync(0xFFFFFFFFu, w, k + 0);
            float w1 = __shfl_sync(0xFFFFFFFFu, w, k + 1);
            float w2 = __shfl_sync(0xFFFFFFFFu, w, k + 2);
            float w3 = __shfl_sync(0xFFFFFFFFu, w, k + 3);
            float2 v0 = *(const float2*)(hfeat + (size_t)s0 * F + hoff);
            float2 v1 = *(const float2*)(hfeat + (size_t)s1 * F + hoff);
            float2 v2 = *(const float2*)(hfeat + (size_t)s2 * F + hoff);
            float2 v3 = *(const float2*)(hfeat + (size_t)s3 * F + hoff);
            a0 += w0 * v0.x + w1 * v1.x + w2 * v2.x + w3 * v3.x;
            a1 += w0 * v0.y + w1 * v1.y + w2 * v2.y + w3 * v3.y;
        }
        for (; k < n; k++) {
            int sk = __shfl_sync(0xFFFFFFFFu, s, k);
            float wk = __shfl_sync(0xFFFFFFFFu, w, k);
            float2 vk = *(const float2*)(hfeat + (size_t)sk * F + hoff);
            a0 += wk * vk.x;
            a1 += wk * vk.y;
        }
    }

    // final denominator
    float ss = ssl;
    #pragma unroll
    for (int o = 16; o > 0; o >>= 1) ss += __shfl_xor_sync(0xFFFFFFFFu, ss, o);
    float inv = 1.f / (ss + 1e-16f);

    float2 bv = *(const float2*)(bias + hoff);
    float o0 = a0 * inv + bv.x;
    float o1 = a1 * inv + bv.y;
    if (ELU) {
        o0 = (o0 > 0.f) ? o0 : expm1f(o0);
        o1 = (o1 > 0.f) ? o1 : expm1f(o1);
    }
    *(float2*)(out + (size_t)d * F + hoff) = make_float2(o0, o1);
}

// ---------------- launch ----------------
extern "C" void kernel_launch(void* const* d_in, const int* in_sizes, int n_in,
                              void* d_out, int out_size) {
    const float* x   = (const float*)d_in[0];
    const int*   ei  = (const int*)d_in[1];
    const float* ea  = (const float*)d_in[2];
    const float* W1  = (const float*)d_in[3];
    const float* We1 = (const float*)d_in[4];
    const float* as1 = (const float*)d_in[5];
    const float* ad1 = (const float*)d_in[6];
    const float* ae1 = (const float*)d_in[7];
    const float* b1  = (const float*)d_in[8];
    const float* W2  = (const float*)d_in[9];
    const float* We2 = (const float*)d_in[10];
    const float* as2 = (const float*)d_in[11];
    const float* ad2 = (const float*)d_in[12];
    const float* ae2 = (const float*)d_in[13];
    const float* b2  = (const float*)d_in[14];
    float* out = (float*)d_out;

    void* p;
    #define SYM(var, sym) cudaGetSymbolAddress(&p, sym); auto* var = (decltype(&sym[0]))p
    SYM(h1, g_h1);       SYM(out1, g_out1);   SYM(h2, g_h2);
    SYM(ssrc1, g_ssrc1); SYM(sdst1, g_sdst1);
    SYM(ssrc2, g_ssrc2); SYM(sdst2, g_sdst2);
    SYM(asum, g_asum);   SYM(deg, g_deg);
    SYM(part, g_part);   SYM(bsum, g_bsum);   SYM(off, g_off);
    SYM(fill, g_fill);   SYM(csrc, g_csrc);   SYM(cea, g_cea);
    SYM(ce1, g_ce1);     SYM(ce2, g_ce2);
    #undef SYM

    const int NB_E  = (N_EDGES + 255) / 256;
    const int GB_M  = (N_NODES + 127) / 128;                    // 391
    const int NB_A1 = ((N_NODES * HH1) * 32 + 255) / 256;       // warp per (node,head)
    const int NB_A2 = ((N_NODES * HH2) * 32 + 255) / 256;

    // --- CSR build (degree -> scan -> scatter; self-loop at slot 0) ---
    init_pre<<<NBLK_N, 256>>>(deg, asum);
    edge_stats<<<NB_E, 256>>>(ei, ea, deg, asum);
    scan_block<<<NBLK_N, 256>>>(deg, part, bsum);
    scan_tops<<<1, 256>>>(bsum);
    scan_final_selfloop<<<NBLK_N, 256>>>(part, bsum, deg, asum, off, csrc, cea, fill);
    csr_fill<<<NB_E, 256>>>(ei, ea, off, fill, csrc, cea);

    // --- layer 1 ---
    gemm_score_kernel<IN_DIM, F1, 128, 8, HH1>
        <<<dim3(GB_M, F1 / 128), 256>>>(x, W1, h1, as1, ad1, ssrc1, sdst1);
    ce_kernel<HH1, CC1><<<1, 32 * HH1>>>(We1, ae1, ce1);
    node_agg<HH1, CC1, true><<<NB_A1, 256>>>(off, csrc, cea, ssrc1, sdst1, ce1, h1, b1, out1);

    // --- layer 2 ---
    gemm_score_kernel<F1, F2, 64, 4, HH2>
        <<<dim3(GB_M, F2 / 64), 256>>>(out1, W2, h2, as2, ad2, ssrc2, sdst2);
    ce_kernel<HH2, CC2><<<1, 32 * HH2>>>(We2, ae2, ce2);
    node_agg<HH2, CC2, false><<<NB_A2, 256>>>(off, csrc, cea, ssrc2, sdst2, ce2, h2, b2, out);
}

// round 8
// speedup vs baseline: 1.4193x; 1.4193x over previous
#include <cuda_runtime.h>
#include <math.h>

#define N_NODES 50000
#define N_EDGES 500000
#define E2 (N_EDGES + N_NODES)   // edges + self loops
#define IN_DIM 128
#define F1 256
#define HH1 4
#define CC1 64
#define F2 64
#define HH2 1
#define CC2 64
#define NBLK_N 196               // ceil(50000/256)

// ---------------- scratch (static device globals; no allocation) ----------------
__device__ float g_h1[(size_t)N_NODES * F1];
__device__ float g_out1[(size_t)N_NODES * F1];
__device__ float g_h2[(size_t)N_NODES * F2];
__device__ float g_ssrc1[N_NODES * HH1];
__device__ float g_sdst1[N_NODES * HH1];
__device__ float g_ssrc2[N_NODES * HH2];
__device__ float g_sdst2[N_NODES * HH2];
__device__ float g_asum[N_NODES];
__device__ int   g_deg[N_NODES];
__device__ int   g_part[N_NODES];
__device__ int   g_bsum[256];
__device__ int   g_off[N_NODES + 1];
__device__ int   g_fill[N_NODES];
__device__ int   g_csrc[E2];
__device__ float g_cea[E2];
__device__ float g_ce1[HH1];
__device__ float g_ce2[HH2];

// ---------------- pre: degree + edge-attr stats ----------------
__global__ void init_pre(int* deg, float* asum) {
    int i = blockIdx.x * blockDim.x + threadIdx.x;
    if (i < N_NODES) { deg[i] = 0; asum[i] = 0.f; }
}

__global__ void edge_stats(const int* __restrict__ ei, const float* __restrict__ ea,
                           int* __restrict__ deg, float* __restrict__ asum) {
    int j = blockIdx.x * blockDim.x + threadIdx.x;
    if (j >= N_EDGES) return;
    int d = ei[N_EDGES + j];
    atomicAdd(&deg[d], 1);
    atomicAdd(&asum[d], ea[j]);
}

// ---------------- 3-kernel exclusive scan of (deg+1) -> CSR offsets ----------------
__global__ void scan_block(const int* __restrict__ deg, int* __restrict__ part,
                           int* __restrict__ bsum) {
    __shared__ int sh[256];
    int i = blockIdx.x * 256 + threadIdx.x;
    int v = (i < N_NODES) ? deg[i] + 1 : 0;
    sh[threadIdx.x] = v;
    __syncthreads();
    for (int o = 1; o < 256; o <<= 1) {
        int t = (threadIdx.x >= o) ? sh[threadIdx.x - o] : 0;
        __syncthreads();
        sh[threadIdx.x] += t;
        __syncthreads();
    }
    if (i < N_NODES) part[i] = sh[threadIdx.x] - v;   // exclusive within block
    if (threadIdx.x == 255) bsum[blockIdx.x] = sh[255];
}

__global__ void scan_tops(int* bsum) {  // 1 block; NBLK_N <= 256
    __shared__ int sh[256];
    int v = (threadIdx.x < NBLK_N) ? bsum[threadIdx.x] : 0;
    sh[threadIdx.x] = v;
    __syncthreads();
    for (int o = 1; o < 256; o <<= 1) {
        int t = (threadIdx.x >= o) ? sh[threadIdx.x - o] : 0;
        __syncthreads();
        sh[threadIdx.x] += t;
        __syncthreads();
    }
    if (threadIdx.x < NBLK_N) bsum[threadIdx.x] = sh[threadIdx.x] - v;  // exclusive
}

// offsets + self-loop (slot 0) + loop-attr, fused
__global__ void scan_final_selfloop(const int* __restrict__ part, const int* __restrict__ bsum,
                                    const int* __restrict__ deg, const float* __restrict__ asum,
                                    int* __restrict__ off, int* __restrict__ csrc,
                                    float* __restrict__ cea, int* __restrict__ fill) {
    int i = blockIdx.x * 256 + threadIdx.x;
    if (i < N_NODES) {
        int o = part[i] + bsum[blockIdx.x];
        off[i] = o;
        csrc[o] = i;
        cea[o] = asum[i] / fmaxf((float)deg[i], 1.f);
        fill[i] = 1;
    }
    if (i == 0) off[N_NODES] = E2;
}

__global__ void csr_fill(const int* __restrict__ ei, const float* __restrict__ ea,
                         const int* __restrict__ off, int* __restrict__ fill,
                         int* __restrict__ csrc, float* __restrict__ cea) {
    int j = blockIdx.x * blockDim.x + threadIdx.x;
    if (j >= N_EDGES) return;
    int d = ei[N_EDGES + j];
    int p = off[d] + atomicAdd(&fill[d], 1);
    csrc[p] = ei[j];
    cea[p] = ea[j];
}

// ---------------- GEMM (R4 mainloop) + fused attention-score epilogue ----------------
// C[M,NC] = A[M,K] @ B[K,NC]; BM=128, BK=32, TM=8; epilogue writes
// ssrc[row,h] = sum_c C[row, h*64+c] * a_src[h*64+c], sdst likewise.
template <int K, int NC, int BN, int TN, int H>
__global__ __launch_bounds__(256) void gemm_score_kernel(
    const float* __restrict__ A, const float* __restrict__ B, float* __restrict__ C,
    const float* __restrict__ a_src, const float* __restrict__ a_dst,
    float* __restrict__ ssrc, float* __restrict__ sdst) {
    const int BM = 128, BK = 32, TM = 8;
    const int TX = BN / TN;  // 16
    __shared__ float As[BK][BM + 4];  // [k][m]
    __shared__ float Bs[BK][BN];      // [k][c]

    const int tid = threadIdx.x;
    const int tx = tid % TX, ty = tid / TX;
    const int mbase = blockIdx.x * BM, cbase = blockIdx.y * BN;
    const int lane = tid & 31;

    float acc[TM][TN] = {};

    for (int kc = 0; kc < K; kc += BK) {
        // stage A (transposed): BM*BK/4 = 1024 float4; 4 per thread
        #pragma unroll
        for (int r = 0; r < (BM * BK / 4) / 256; r++) {
            int f = tid + r * 256;
            int row = f >> 3, kq = f & 7;
            int gm = mbase + row;
            float4 v = make_float4(0.f, 0.f, 0.f, 0.f);
            if (gm < N_NODES) v = *(const float4*)(A + (size_t)gm * K + kc + kq * 4);
            As[kq * 4 + 0][row] = v.x;
            As[kq * 4 + 1][row] = v.y;
            As[kq * 4 + 2][row] = v.z;
            As[kq * 4 + 3][row] = v.w;
        }
        // stage B direct
        #pragma unroll
        for (int r = 0; r < (BK * BN / 4) / 256; r++) {
            int f = tid + r * 256;
            int c4 = f % (BN / 4), kr = f / (BN / 4);
            *(float4*)&Bs[kr][c4 * 4] =
                *(const float4*)(B + (size_t)(kc + kr) * NC + cbase + c4 * 4);
        }
        __syncthreads();
        #pragma unroll
        for (int k = 0; k < BK; k++) {
            float a[TM], b[TN];
            #pragma unroll
            for (int i = 0; i < TM; i += 4) *(float4*)&a[i] = *(const float4*)&As[k][ty * TM + i];
            #pragma unroll
            for (int j = 0; j < TN; j += 4) *(float4*)&b[j] = *(const float4*)&Bs[k][tx * TN + j];
            #pragma unroll
            for (int i = 0; i < TM; i++)
                #pragma unroll
                for (int j = 0; j < TN; j++) acc[i][j] += a[i] * b[j];
        }
        __syncthreads();
    }

    // store C tile
    #pragma unroll
    for (int i = 0; i < TM; i++) {
        int gm = mbase + ty * TM + i;
        if (gm < N_NODES) {
            #pragma unroll
            for (int j = 0; j < TN; j += 4)
                *(float4*)(C + (size_t)gm * NC + cbase + tx * TN + j) =
                    make_float4(acc[i][j], acc[i][j + 1], acc[i][j + 2], acc[i][j + 3]);
        }
    }

    // fused score epilogue: TPH lanes share one (row, head)
    const int CPH = 64;                 // channels per head
    const int TPH = CPH / TN;           // 8 (BN=128) or 16 (BN=64)
    float av[TN], dv[TN];
    #pragma unroll
    for (int j = 0; j < TN; j++) {
        av[j] = __ldg(a_src + cbase + tx * TN + j);
        dv[j] = __ldg(a_dst + cbase + tx * TN + j);
    }
    const int head = (cbase + tx * TN) / CPH;
    #pragma unroll
    for (int i = 0; i < TM; i++) {
        float ps = 0.f, pd = 0.f;
        #pragma unroll
        for (int j = 0; j < TN; j++) { ps += acc[i][j] * av[j]; pd += acc[i][j] * dv[j]; }
        #pragma unroll
        for (int o = 1; o < TPH; o <<= 1) {
            ps += __shfl_xor_sync(0xFFFFFFFFu, ps, o);
            pd += __shfl_xor_sync(0xFFFFFFFFu, pd, o);
        }
        int gm = mbase + ty * TM + i;
        if ((lane % TPH) == 0 && gm < N_NODES) {
            ssrc[(size_t)gm * H + head] = ps;
            sdst[(size_t)gm * H + head] = pd;
        }
    }
}

// ---------------- ce[h] = dot(We[h*C..], ae[h*C..]) ----------------
template <int H, int C>
__global__ void ce_kernel(const float* __restrict__ We, const float* __restrict__ ae,
                          float* __restrict__ ce) {
    int h = threadIdx.x >> 5;
    int lane = threadIdx.x & 31;
    float s = 0.f;
    for (int c = lane; c < C; c += 32) s += We[h * C + c] * ae[h * C + c];
    #pragma unroll
    for (int off = 16; off > 0; off >>= 1) s += __shfl_xor_sync(0xFFFFFFFFu, s, off);
    if (lane == 0) ce[h] = s;
}

// ---------------- fused softmax + aggregation + bias(+ELU): warp per dst node ----------------
template <int H, int C, bool ELU>
__global__ __launch_bounds__(256) void node_agg(
    const int* __restrict__ off, const int* __restrict__ csrc, const float* __restrict__ cea,
    const float* __restrict__ ssrc, const float* __restrict__ sdst, const float* __restrict__ ce,
    const float* __restrict__ hfeat, const float* __restrict__ bias, float* __restrict__ out) {
    const int F = H * C, PER = F / 32;
    int d = (blockIdx.x * blockDim.x + threadIdx.x) >> 5;
    int lane = threadIdx.x & 31;
    if (d >= N_NODES) return;

    int e0 = off[d], e1 = off[d + 1];

    float sd[H], cv[H];
    #pragma unroll
    for (int h = 0; h < H; h++) { sd[h] = sdst[(size_t)d * H + h]; cv[h] = ce[h]; }

    // phase 1: online softmax (max + denom) over this node's edges
    float m[H], ss[H];
    #pragma unroll
    for (int h = 0; h < H; h++) { m[h] = -1e30f; ss[h] = 0.f; }

    for (int e = e0 + lane; e < e1; e += 32) {
        int s = csrc[e];
        float a = cea[e];
        float sv[H];
        if (H == 4) {
            float4 t = *(const float4*)(ssrc + (size_t)s * 4);
            sv[0] = t.x; sv[1] = t.y; sv[2] = t.z; sv[3] = t.w;
        } else {
            sv[0] = ssrc[s];
        }
        #pragma unroll
        for (int h = 0; h < H; h++) {
            float v = sv[h] + sd[h] + a * cv[h];
            v = (v >= 0.f) ? v : 0.2f * v;
            float nm = fmaxf(m[h], v);
            ss[h] = ss[h] * __expf(m[h] - nm) + __expf(v - nm);
            m[h] = nm;
        }
    }
    #pragma unroll
    for (int o = 16; o > 0; o >>= 1) {
        #pragma unroll
        for (int h = 0; h < H; h++) {
            float m2 = __shfl_xor_sync(0xFFFFFFFFu, m[h], o);
            float s2 = __shfl_xor_sync(0xFFFFFFFFu, ss[h], o);
            float nm = fmaxf(m[h], m2);
            ss[h] = ss[h] * __expf(m[h] - nm) + s2 * __expf(m2 - nm);
            m[h] = nm;
        }
    }

    // select this lane's head constants (compile-time unrolled)
    const int hme = (lane * PER) / C;
    float my_m = m[0], my_s = ss[0], my_sd = sd[0], my_ce = cv[0];
    #pragma unroll
    for (int h = 1; h < H; h++)
        if (hme == h) { my_m = m[h]; my_s = ss[h]; my_sd = sd[h]; my_ce = cv[h]; }
    float inv = 1.f / (my_s + 1e-16f);

    // phase 2: weighted gather-accumulate, 2 edges in flight
    float acc[PER];
    #pragma unroll
    for (int i = 0; i < PER; i++) acc[i] = 0.f;

    int e = e0;
    for (; e + 2 <= e1; e += 2) {
        int s0 = csrc[e], s1 = csrc[e + 1];
        float aa0 = cea[e], aa1 = cea[e + 1];
        float v0 = ssrc[(size_t)s0 * H + hme] + my_sd + aa0 * my_ce;
        float v1 = ssrc[(size_t)s1 * H + hme] + my_sd + aa1 * my_ce;
        v0 = (v0 >= 0.f) ? v0 : 0.2f * v0;
        v1 = (v1 >= 0.f) ? v1 : 0.2f * v1;
        float c0 = __expf(v0 - my_m) * inv;
        float c1 = __expf(v1 - my_m) * inv;
        const float* sp0 = hfeat + (size_t)s0 * F + lane * PER;
        const float* sp1 = hfeat + (size_t)s1 * F + lane * PER;
        if (PER == 8) {
            float4 x0 = *(const float4*)sp0;
            float4 x1 = *(const float4*)(sp0 + 4);
            float4 y0 = *(const float4*)sp1;
            float4 y1 = *(const float4*)(sp1 + 4);
            acc[0] += c0 * x0.x + c1 * y0.x; acc[1] += c0 * x0.y + c1 * y0.y;
            acc[2] += c0 * x0.z + c1 * y0.z; acc[3] += c0 * x0.w + c1 * y0.w;
            acc[4] += c0 * x1.x + c1 * y1.x; acc[5] += c0 * x1.y + c1 * y1.y;
            acc[6] += c0 * x1.z + c1 * y1.z; acc[7] += c0 * x1.w + c1 * y1.w;
        } else {
            float2 x0 = *(const float2*)sp0;
            float2 y0 = *(const float2*)sp1;
            acc[0] += c0 * x0.x + c1 * y0.x;
            acc[1] += c0 * x0.y + c1 * y0.y;
        }
    }
    for (; e < e1; e++) {
        int s = csrc[e];
        float a = cea[e];
        float v = ssrc[(size_t)s * H + hme] + my_sd + a * my_ce;
        v = (v >= 0.f) ? v : 0.2f * v;
        float coef = __expf(v - my_m) * inv;
        const float* sp = hfeat + (size_t)s * F + lane * PER;
        if (PER == 8) {
            float4 v0 = *(const float4*)sp;
            float4 v1 = *(const float4*)(sp + 4);
            acc[0] += coef * v0.x; acc[1] += coef * v0.y;
            acc[2] += coef * v0.z; acc[3] += coef * v0.w;
            acc[4] += coef * v1.x; acc[5] += coef * v1.y;
            acc[6] += coef * v1.z; acc[7] += coef * v1.w;
        } else {
            float2 v0 = *(const float2*)sp;
            acc[0] += coef * v0.x; acc[1] += coef * v0.y;
        }
    }

    // epilogue: bias (+ELU), single plain store
    float* op = out + (size_t)d * F + lane * PER;
    #pragma unroll
    for (int i = 0; i < PER; i++) {
        float v = acc[i] + bias[lane * PER + i];
        if (ELU) v = (v > 0.f) ? v : expm1f(v);
        op[i] = v;
    }
}

// ---------------- launch ----------------
extern "C" void kernel_launch(void* const* d_in, const int* in_sizes, int n_in,
                              void* d_out, int out_size) {
    const float* x   = (const float*)d_in[0];
    const int*   ei  = (const int*)d_in[1];
    const float* ea  = (const float*)d_in[2];
    const float* W1  = (const float*)d_in[3];
    const float* We1 = (const float*)d_in[4];
    const float* as1 = (const float*)d_in[5];
    const float* ad1 = (const float*)d_in[6];
    const float* ae1 = (const float*)d_in[7];
    const float* b1  = (const float*)d_in[8];
    const float* W2  = (const float*)d_in[9];
    const float* We2 = (const float*)d_in[10];
    const float* as2 = (const float*)d_in[11];
    const float* ad2 = (const float*)d_in[12];
    const float* ae2 = (const float*)d_in[13];
    const float* b2  = (const float*)d_in[14];
    float* out = (float*)d_out;

    void* p;
    #define SYM(var, sym) cudaGetSymbolAddress(&p, sym); auto* var = (decltype(&sym[0]))p
    SYM(h1, g_h1);       SYM(out1, g_out1);   SYM(h2, g_h2);
    SYM(ssrc1, g_ssrc1); SYM(sdst1, g_sdst1);
    SYM(ssrc2, g_ssrc2); SYM(sdst2, g_sdst2);
    SYM(asum, g_asum);   SYM(deg, g_deg);
    SYM(part, g_part);   SYM(bsum, g_bsum);   SYM(off, g_off);
    SYM(fill, g_fill);   SYM(csrc, g_csrc);   SYM(cea, g_cea);
    SYM(ce1, g_ce1);     SYM(ce2, g_ce2);
    #undef SYM

    const int NB_E  = (N_EDGES + 255) / 256;
    const int NB_NW = (N_NODES * 32 + 255) / 256;  // warp-per-node kernels
    const int GB_M  = (N_NODES + 127) / 128;       // 391

    // --- CSR build (degree -> scan -> scatter; self-loop at slot 0) ---
    init_pre<<<NBLK_N, 256>>>(deg, asum);
    edge_stats<<<NB_E, 256>>>(ei, ea, deg, asum);
    scan_block<<<NBLK_N, 256>>>(deg, part, bsum);
    scan_tops<<<1, 256>>>(bsum);
    scan_final_selfloop<<<NBLK_N, 256>>>(part, bsum, deg, asum, off, csrc, cea, fill);
    csr_fill<<<NB_E, 256>>>(ei, ea, off, fill, csrc, cea);

    // --- layer 1 ---
    gemm_score_kernel<IN_DIM, F1, 128, 8, HH1>
        <<<dim3(GB_M, F1 / 128), 256>>>(x, W1, h1, as1, ad1, ssrc1, sdst1);
    ce_kernel<HH1, CC1><<<1, 32 * HH1>>>(We1, ae1, ce1);
    node_agg<HH1, CC1, true><<<NB_NW, 256>>>(off, csrc, cea, ssrc1, sdst1, ce1, h1, b1, out1);

    // --- layer 2 ---
    gemm_score_kernel<F1, F2, 64, 4, HH2>
        <<<dim3(GB_M, F2 / 64), 256>>>(out1, W2, h2, as2, ad2, ssrc2, sdst2);
    ce_kernel<HH2, CC2><<<1, 32 * HH2>>>(We2, ae2, ce2);
    node_agg<HH2, CC2, false><<<NB_NW, 256>>>(off, csrc, cea, ssrc2, sdst2, ce2, h2, b2, out);
}

// round 10
// speedup vs baseline: 1.4223x; 1.0021x over previous
#include <cuda_runtime.h>
#include <math.h>

#define N_NODES 50000
#define N_EDGES 500000
#define E2 (N_EDGES + N_NODES)   // edges + self loops
#define IN_DIM 128
#define F1 256
#define HH1 4
#define CC1 64
#define F2 64
#define HH2 1
#define CC2 64
#define NBLK_N 196               // ceil(50000/256)

// ---------------- scratch (static device globals; no allocation) ----------------
__device__ float g_h1[(size_t)N_NODES * F1];
__device__ float g_out1[(size_t)N_NODES * F1];
__device__ float g_h2[(size_t)N_NODES * F2];
__device__ float g_ssrc1[N_NODES * HH1];
__device__ float g_sdst1[N_NODES * HH1];
__device__ float g_ssrc2[N_NODES * HH2];
__device__ float g_sdst2[N_NODES * HH2];
__device__ float g_asum[N_NODES];
__device__ int   g_deg[N_NODES];
__device__ int   g_part[N_NODES];
__device__ int   g_bsum[256];
__device__ int   g_off[N_NODES + 1];
__device__ int   g_fill[N_NODES];
__device__ int   g_csrc[E2];
__device__ float g_cea[E2];
__device__ float g_ce1[HH1];
__device__ float g_ce2[HH2];

// ---------------- pre: degree + edge-attr stats ----------------
__global__ void init_pre(int* deg, float* asum) {
    int i = blockIdx.x * blockDim.x + threadIdx.x;
    if (i < N_NODES) { deg[i] = 0; asum[i] = 0.f; }
}

__global__ void edge_stats(const int* __restrict__ ei, const float* __restrict__ ea,
                           int* __restrict__ deg, float* __restrict__ asum) {
    int j = blockIdx.x * blockDim.x + threadIdx.x;
    if (j >= N_EDGES) return;
    int d = ei[N_EDGES + j];
    atomicAdd(&deg[d], 1);
    atomicAdd(&asum[d], ea[j]);
}

// ---------------- 3-kernel exclusive scan of (deg+1) -> CSR offsets ----------------
__global__ void scan_block(const int* __restrict__ deg, int* __restrict__ part,
                           int* __restrict__ bsum) {
    __shared__ int sh[256];
    int i = blockIdx.x * 256 + threadIdx.x;
    int v = (i < N_NODES) ? deg[i] + 1 : 0;
    sh[threadIdx.x] = v;
    __syncthreads();
    for (int o = 1; o < 256; o <<= 1) {
        int t = (threadIdx.x >= o) ? sh[threadIdx.x - o] : 0;
        __syncthreads();
        sh[threadIdx.x] += t;
        __syncthreads();
    }
    if (i < N_NODES) part[i] = sh[threadIdx.x] - v;   // exclusive within block
    if (threadIdx.x == 255) bsum[blockIdx.x] = sh[255];
}

__global__ void scan_tops(int* bsum) {  // 1 block; NBLK_N <= 256
    __shared__ int sh[256];
    int v = (threadIdx.x < NBLK_N) ? bsum[threadIdx.x] : 0;
    sh[threadIdx.x] = v;
    __syncthreads();
    for (int o = 1; o < 256; o <<= 1) {
        int t = (threadIdx.x >= o) ? sh[threadIdx.x - o] : 0;
        __syncthreads();
        sh[threadIdx.x] += t;
        __syncthreads();
    }
    if (threadIdx.x < NBLK_N) bsum[threadIdx.x] = sh[threadIdx.x] - v;  // exclusive
}

// offsets + self-loop (slot 0) + loop-attr, fused
__global__ void scan_final_selfloop(const int* __restrict__ part, const int* __restrict__ bsum,
                                    const int* __restrict__ deg, const float* __restrict__ asum,
                                    int* __restrict__ off, int* __restrict__ csrc,
                                    float* __restrict__ cea, int* __restrict__ fill) {
    int i = blockIdx.x * 256 + threadIdx.x;
    if (i < N_NODES) {
        int o = part[i] + bsum[blockIdx.x];
        off[i] = o;
        csrc[o] = i;
        cea[o] = asum[i] / fmaxf((float)deg[i], 1.f);
        fill[i] = 1;
    }
    if (i == 0) off[N_NODES] = E2;
}

__global__ void csr_fill(const int* __restrict__ ei, const float* __restrict__ ea,
                         const int* __restrict__ off, int* __restrict__ fill,
                         int* __restrict__ csrc, float* __restrict__ cea) {
    int j = blockIdx.x * blockDim.x + threadIdx.x;
    if (j >= N_EDGES) return;
    int d = ei[N_EDGES + j];
    int p = off[d] + atomicAdd(&fill[d], 1);
    csrc[p] = ei[j];
    cea[p] = ea[j];
}

// ---------------- GEMM (R4 mainloop) + fused attention-score epilogue ----------------
// C[M,NC] = A[M,K] @ B[K,NC]; BM=128, BK=32, TM=8; epilogue writes
// ssrc[row,h] = sum_c C[row, h*64+c] * a_src[h*64+c], sdst likewise.
template <int K, int NC, int BN, int TN, int H>
__global__ __launch_bounds__(256) void gemm_score_kernel(
    const float* __restrict__ A, const float* __restrict__ B, float* __restrict__ C,
    const float* __restrict__ a_src, const float* __restrict__ a_dst,
    float* __restrict__ ssrc, float* __restrict__ sdst) {
    const int BM = 128, BK = 32, TM = 8;
    const int TX = BN / TN;  // 16
    __shared__ float As[BK][BM + 4];  // [k][m]
    __shared__ float Bs[BK][BN];      // [k][c]

    const int tid = threadIdx.x;
    const int tx = tid % TX, ty = tid / TX;
    const int mbase = blockIdx.x * BM, cbase = blockIdx.y * BN;
    const int lane = tid & 31;

    float acc[TM][TN] = {};

    for (int kc = 0; kc < K; kc += BK) {
        // stage A (transposed): BM*BK/4 = 1024 float4; 4 per thread
        #pragma unroll
        for (int r = 0; r < (BM * BK / 4) / 256; r++) {
            int f = tid + r * 256;
            int row = f >> 3, kq = f & 7;
            int gm = mbase + row;
            float4 v = make_float4(0.f, 0.f, 0.f, 0.f);
            if (gm < N_NODES) v = *(const float4*)(A + (size_t)gm * K + kc + kq * 4);
            As[kq * 4 + 0][row] = v.x;
            As[kq * 4 + 1][row] = v.y;
            As[kq * 4 + 2][row] = v.z;
            As[kq * 4 + 3][row] = v.w;
        }
        // stage B direct
        #pragma unroll
        for (int r = 0; r < (BK * BN / 4) / 256; r++) {
            int f = tid + r * 256;
            int c4 = f % (BN / 4), kr = f / (BN / 4);
            *(float4*)&Bs[kr][c4 * 4] =
                *(const float4*)(B + (size_t)(kc + kr) * NC + cbase + c4 * 4);
        }
        __syncthreads();
        #pragma unroll
        for (int k = 0; k < BK; k++) {
            float a[TM], b[TN];
            #pragma unroll
            for (int i = 0; i < TM; i += 4) *(float4*)&a[i] = *(const float4*)&As[k][ty * TM + i];
            #pragma unroll
            for (int j = 0; j < TN; j += 4) *(float4*)&b[j] = *(const float4*)&Bs[k][tx * TN + j];
            #pragma unroll
            for (int i = 0; i < TM; i++)
                #pragma unroll
                for (int j = 0; j < TN; j++) acc[i][j] += a[i] * b[j];
        }
        __syncthreads();
    }

    // store C tile
    #pragma unroll
    for (int i = 0; i < TM; i++) {
        int gm = mbase + ty * TM + i;
        if (gm < N_NODES) {
            #pragma unroll
            for (int j = 0; j < TN; j += 4)
                *(float4*)(C + (size_t)gm * NC + cbase + tx * TN + j) =
                    make_float4(acc[i][j], acc[i][j + 1], acc[i][j + 2], acc[i][j + 3]);
        }
    }

    // fused score epilogue: TPH lanes share one (row, head)
    const int CPH = 64;                 // channels per head
    const int TPH = CPH / TN;           // 8 (BN=128) or 16 (BN=64)
    float av[TN], dv[TN];
    #pragma unroll
    for (int j = 0; j < TN; j++) {
        av[j] = __ldg(a_src + cbase + tx * TN + j);
        dv[j] = __ldg(a_dst + cbase + tx * TN + j);
    }
    const int head = (cbase + tx * TN) / CPH;
    #pragma unroll
    for (int i = 0; i < TM; i++) {
        float ps = 0.f, pd = 0.f;
        #pragma unroll
        for (int j = 0; j < TN; j++) { ps += acc[i][j] * av[j]; pd += acc[i][j] * dv[j]; }
        #pragma unroll
        for (int o = 1; o < TPH; o <<= 1) {
            ps += __shfl_xor_sync(0xFFFFFFFFu, ps, o);
            pd += __shfl_xor_sync(0xFFFFFFFFu, pd, o);
        }
        int gm = mbase + ty * TM + i;
        if ((lane % TPH) == 0 && gm < N_NODES) {
            ssrc[(size_t)gm * H + head] = ps;
            sdst[(size_t)gm * H + head] = pd;
        }
    }
}

// ---------------- ce[h] = dot(We[h*C..], ae[h*C..]) ----------------
template <int H, int C>
__global__ void ce_kernel(const float* __restrict__ We, const float* __restrict__ ae,
                          float* __restrict__ ce) {
    int h = threadIdx.x >> 5;
    int lane = threadIdx.x & 31;
    float s = 0.f;
    for (int c = lane; c < C; c += 32) s += We[h * C + c] * ae[h * C + c];
    #pragma unroll
    for (int off = 16; off > 0; off >>= 1) s += __shfl_xor_sync(0xFFFFFFFFu, s, off);
    if (lane == 0) ce[h] = s;
}

// ---------------- fused softmax + aggregation + bias(+ELU): warp per dst node ----------------
template <int H, int C, bool ELU>
__global__ __launch_bounds__(256) void node_agg(
    const int* __restrict__ off, const int* __restrict__ csrc, const float* __restrict__ cea,
    const float* __restrict__ ssrc, const float* __restrict__ sdst, const float* __restrict__ ce,
    const float* __restrict__ hfeat, const float* __restrict__ bias, float* __restrict__ out) {
    const int F = H * C, PER = F / 32;
    int d = (blockIdx.x * blockDim.x + threadIdx.x) >> 5;
    int lane = threadIdx.x & 31;
    if (d >= N_NODES) return;

    int e0 = off[d], e1 = off[d + 1];

    float sd[H], cv[H];
    #pragma unroll
    for (int h = 0; h < H; h++) { sd[h] = sdst[(size_t)d * H + h]; cv[h] = ce[h]; }

    // phase 1: online softmax (max + denom) over this node's edges
    float m[H], ss[H];
    #pragma unroll
    for (int h = 0; h < H; h++) { m[h] = -1e30f; ss[h] = 0.f; }

    for (int e = e0 + lane; e < e1; e += 32) {
        int s = csrc[e];
        float a = cea[e];
        float sv[H];
        if (H == 4) {
            float4 t = *(const float4*)(ssrc + (size_t)s * 4);
            sv[0] = t.x; sv[1] = t.y; sv[2] = t.z; sv[3] = t.w;
        } else {
            sv[0] = ssrc[s];
        }
        #pragma unroll
        for (int h = 0; h < H; h++) {
            float v = sv[h] + sd[h] + a * cv[h];
            v = (v >= 0.f) ? v : 0.2f * v;
            float nm = fmaxf(m[h], v);
            ss[h] = ss[h] * __expf(m[h] - nm) + __expf(v - nm);
            m[h] = nm;
        }
    }
    #pragma unroll
    for (int o = 16; o > 0; o >>= 1) {
        #pragma unroll
        for (int h = 0; h < H; h++) {
            float m2 = __shfl_xor_sync(0xFFFFFFFFu, m[h], o);
            float s2 = __shfl_xor_sync(0xFFFFFFFFu, ss[h], o);
            float nm = fmaxf(m[h], m2);
            ss[h] = ss[h] * __expf(m[h] - nm) + s2 * __expf(m2 - nm);
            m[h] = nm;
        }
    }

    // select this lane's head constants (compile-time unrolled)
    const int hme = (lane * PER) / C;
    float my_m = m[0], my_s = ss[0], my_sd = sd[0], my_ce = cv[0];
    #pragma unroll
    for (int h = 1; h < H; h++)
        if (hme == h) { my_m = m[h]; my_s = ss[h]; my_sd = sd[h]; my_ce = cv[h]; }
    float inv = 1.f / (my_s + 1e-16f);

    // phase 2: weighted gather-accumulate, 2 edges in flight
    float acc[PER];
    #pragma unroll
    for (int i = 0; i < PER; i++) acc[i] = 0.f;

    int e = e0;
    for (; e + 2 <= e1; e += 2) {
        int s0 = csrc[e], s1 = csrc[e + 1];
        float aa0 = cea[e], aa1 = cea[e + 1];
        float v0 = ssrc[(size_t)s0 * H + hme] + my_sd + aa0 * my_ce;
        float v1 = ssrc[(size_t)s1 * H + hme] + my_sd + aa1 * my_ce;
        v0 = (v0 >= 0.f) ? v0 : 0.2f * v0;
        v1 = (v1 >= 0.f) ? v1 : 0.2f * v1;
        float c0 = __expf(v0 - my_m) * inv;
        float c1 = __expf(v1 - my_m) * inv;
        const float* sp0 = hfeat + (size_t)s0 * F + lane * PER;
        const float* sp1 = hfeat + (size_t)s1 * F + lane * PER;
        if (PER == 8) {
            float4 x0 = *(const float4*)sp0;
            float4 x1 = *(const float4*)(sp0 + 4);
            float4 y0 = *(const float4*)sp1;
            float4 y1 = *(const float4*)(sp1 + 4);
            acc[0] += c0 * x0.x + c1 * y0.x; acc[1] += c0 * x0.y + c1 * y0.y;
            acc[2] += c0 * x0.z + c1 * y0.z; acc[3] += c0 * x0.w + c1 * y0.w;
            acc[4] += c0 * x1.x + c1 * y1.x; acc[5] += c0 * x1.y + c1 * y1.y;
            acc[6] += c0 * x1.z + c1 * y1.z; acc[7] += c0 * x1.w + c1 * y1.w;
        } else {
            float2 x0 = *(const float2*)sp0;
            float2 y0 = *(const float2*)sp1;
            acc[0] += c0 * x0.x + c1 * y0.x;
            acc[1] += c0 * x0.y + c1 * y0.y;
        }
    }
    for (; e < e1; e++) {
        int s = csrc[e];
        float a = cea[e];
        float v = ssrc[(size_t)s * H + hme] + my_sd + a * my_ce;
        v = (v >= 0.f) ? v : 0.2f * v;
        float coef = __expf(v - my_m) * inv;
        const float* sp = hfeat + (size_t)s * F + lane * PER;
        if (PER == 8) {
            float4 v0 = *(const float4*)sp;
            float4 v1 = *(const float4*)(sp + 4);
            acc[0] += coef * v0.x; acc[1] += coef * v0.y;
            acc[2] += coef * v0.z; acc[3] += coef * v0.w;
            acc[4] += coef * v1.x; acc[5] += coef * v1.y;
            acc[6] += coef * v1.z; acc[7] += coef * v1.w;
        } else {
            float2 v0 = *(const float2*)sp;
            acc[0] += coef * v0.x; acc[1] += coef * v0.y;
        }
    }

    // epilogue: bias (+ELU), single plain store
    float* op = out + (size_t)d * F + lane * PER;
    #pragma unroll
    for (int i = 0; i < PER; i++) {
        float v = acc[i] + bias[lane * PER + i];
        if (ELU) v = (v > 0.f) ? v : expm1f(v);
        op[i] = v;
    }
}

// ---------------- launch ----------------
extern "C" void kernel_launch(void* const* d_in, const int* in_sizes, int n_in,
                              void* d_out, int out_size) {
    const float* x   = (const float*)d_in[0];
    const int*   ei  = (const int*)d_in[1];
    const float* ea  = (const float*)d_in[2];
    const float* W1  = (const float*)d_in[3];
    const float* We1 = (const float*)d_in[4];
    const float* as1 = (const float*)d_in[5];
    const float* ad1 = (const float*)d_in[6];
    const float* ae1 = (const float*)d_in[7];
    const float* b1  = (const float*)d_in[8];
    const float* W2  = (const float*)d_in[9];
    const float* We2 = (const float*)d_in[10];
    const float* as2 = (const float*)d_in[11];
    const float* ad2 = (const float*)d_in[12];
    const float* ae2 = (const float*)d_in[13];
    const float* b2  = (const float*)d_in[14];
    float* out = (float*)d_out;

    void* p;
    #define SYM(var, sym) cudaGetSymbolAddress(&p, sym); auto* var = (decltype(&sym[0]))p
    SYM(h1, g_h1);       SYM(out1, g_out1);   SYM(h2, g_h2);
    SYM(ssrc1, g_ssrc1); SYM(sdst1, g_sdst1);
    SYM(ssrc2, g_ssrc2); SYM(sdst2, g_sdst2);
    SYM(asum, g_asum);   SYM(deg, g_deg);
    SYM(part, g_part);   SYM(bsum, g_bsum);   SYM(off, g_off);
    SYM(fill, g_fill);   SYM(csrc, g_csrc);   SYM(cea, g_cea);
    SYM(ce1, g_ce1);     SYM(ce2, g_ce2);
    #undef SYM

    const int NB_E  = (N_EDGES + 255) / 256;
    const int NB_NW = (N_NODES * 32 + 255) / 256;  // warp-per-node kernels
    const int GB_M  = (N_NODES + 127) / 128;       // 391

    // --- CSR build (degree -> scan -> scatter; self-loop at slot 0) ---
    init_pre<<<NBLK_N, 256>>>(deg, asum);
    edge_stats<<<NB_E, 256>>>(ei, ea, deg, asum);
    scan_block<<<NBLK_N, 256>>>(deg, part, bsum);
    scan_tops<<<1, 256>>>(bsum);
    scan_final_selfloop<<<NBLK_N, 256>>>(part, bsum, deg, asum, off, csrc, cea, fill);
    csr_fill<<<NB_E, 256>>>(ei, ea, off, fill, csrc, cea);

    // --- layer 1 ---
    gemm_score_kernel<IN_DIM, F1, 128, 8, HH1>
        <<<dim3(GB_M, F1 / 128), 256>>>(x, W1, h1, as1, ad1, ssrc1, sdst1);
    ce_kernel<HH1, CC1><<<1, 32 * HH1>>>(We1, ae1, ce1);
    node_agg<HH1, CC1, true><<<NB_NW, 256>>>(off, csrc, cea, ssrc1, sdst1, ce1, h1, b1, out1);

    // --- layer 2 ---
    gemm_score_kernel<F1, F2, 64, 4, HH2>
        <<<dim3(GB_M, F2 / 64), 256>>>(out1, W2, h2, as2, ad2, ssrc2, sdst2);
    ce_kernel<HH2, CC2><<<1, 32 * HH2>>>(We2, ae2, ce2);
    node_agg<HH2, CC2, false><<<NB_NW, 256>>>(off, csrc, cea, ssrc2, sdst2, ce2, h2, b2, out);
}

// round 12
// speedup vs baseline: 1.4224x; 1.0001x over previous
#include <cuda_runtime.h>
#include <math.h>

#define N_NODES 50000
#define N_EDGES 500000
#define E2 (N_EDGES + N_NODES)   // edges + self loops
#define IN_DIM 128
#define F1 256
#define HH1 4
#define CC1 64
#define F2 64
#define HH2 1
#define CC2 64
#define NBLK_N 196               // ceil(50000/256)

// ---------------- scratch (static device globals; no allocation) ----------------
__device__ float g_h1[(size_t)N_NODES * F1];
__device__ float g_out1[(size_t)N_NODES * F1];
__device__ float g_h2[(size_t)N_NODES * F2];
__device__ float g_ssrc1[N_NODES * HH1];
__device__ float g_sdst1[N_NODES * HH1];
__device__ float g_ssrc2[N_NODES * HH2];
__device__ float g_sdst2[N_NODES * HH2];
__device__ float g_asum[N_NODES];
__device__ int   g_deg[N_NODES];
__device__ int   g_part[N_NODES];
__device__ int   g_bsum[256];
__device__ int   g_off[N_NODES + 1];
__device__ int   g_fill[N_NODES];
__device__ int   g_csrc[E2];
__device__ float g_cea[E2];
__device__ float g_ce1[HH1];
__device__ float g_ce2[HH2];

// ---------------- pre: degree + edge-attr stats ----------------
__global__ void init_pre(int* deg, float* asum) {
    int i = blockIdx.x * blockDim.x + threadIdx.x;
    if (i < N_NODES) { deg[i] = 0; asum[i] = 0.f; }
}

__global__ void edge_stats(const int* __restrict__ ei, const float* __restrict__ ea,
                           int* __restrict__ deg, float* __restrict__ asum) {
    int j = blockIdx.x * blockDim.x + threadIdx.x;
    if (j >= N_EDGES) return;
    int d = ei[N_EDGES + j];
    atomicAdd(&deg[d], 1);
    atomicAdd(&asum[d], ea[j]);
}

// ---------------- 3-kernel exclusive scan of (deg+1) -> CSR offsets ----------------
__global__ void scan_block(const int* __restrict__ deg, int* __restrict__ part,
                           int* __restrict__ bsum) {
    __shared__ int sh[256];
    int i = blockIdx.x * 256 + threadIdx.x;
    int v = (i < N_NODES) ? deg[i] + 1 : 0;
    sh[threadIdx.x] = v;
    __syncthreads();
    for (int o = 1; o < 256; o <<= 1) {
        int t = (threadIdx.x >= o) ? sh[threadIdx.x - o] : 0;
        __syncthreads();
        sh[threadIdx.x] += t;
        __syncthreads();
    }
    if (i < N_NODES) part[i] = sh[threadIdx.x] - v;   // exclusive within block
    if (threadIdx.x == 255) bsum[blockIdx.x] = sh[255];
}

__global__ void scan_tops(int* bsum) {  // 1 block; NBLK_N <= 256
    __shared__ int sh[256];
    int v = (threadIdx.x < NBLK_N) ? bsum[threadIdx.x] : 0;
    sh[threadIdx.x] = v;
    __syncthreads();
    for (int o = 1; o < 256; o <<= 1) {
        int t = (threadIdx.x >= o) ? sh[threadIdx.x - o] : 0;
        __syncthreads();
        sh[threadIdx.x] += t;
        __syncthreads();
    }
    if (threadIdx.x < NBLK_N) bsum[threadIdx.x] = sh[threadIdx.x] - v;  // exclusive
}

// offsets + self-loop (slot 0) + loop-attr, fused
__global__ void scan_final_selfloop(const int* __restrict__ part, const int* __restrict__ bsum,
                                    const int* __restrict__ deg, const float* __restrict__ asum,
                                    int* __restrict__ off, int* __restrict__ csrc,
                                    float* __restrict__ cea, int* __restrict__ fill) {
    int i = blockIdx.x * 256 + threadIdx.x;
    if (i < N_NODES) {
        int o = part[i] + bsum[blockIdx.x];
        off[i] = o;
        csrc[o] = i;
        cea[o] = asum[i] / fmaxf((float)deg[i], 1.f);
        fill[i] = 1;
    }
    if (i == 0) off[N_NODES] = E2;
}

__global__ void csr_fill(const int* __restrict__ ei, const float* __restrict__ ea,
                         const int* __restrict__ off, int* __restrict__ fill,
                         int* __restrict__ csrc, float* __restrict__ cea) {
    int j = blockIdx.x * blockDim.x + threadIdx.x;
    if (j >= N_EDGES) return;
    int d = ei[N_EDGES + j];
    int p = off[d] + atomicAdd(&fill[d], 1);
    csrc[p] = ei[j];
    cea[p] = ea[j];
}

// ---------------- GEMM (R4 mainloop) + fused attention-score epilogue ----------------
// C[M,NC] = A[M,K] @ B[K,NC]; BM=128, BK=32, TM=8; epilogue writes
// ssrc[row,h] = sum_c C[row, h*64+c] * a_src[h*64+c], sdst likewise.
template <int K, int NC, int BN, int TN, int H>
__global__ __launch_bounds__(256) void gemm_score_kernel(
    const float* __restrict__ A, const float* __restrict__ B, float* __restrict__ C,
    const float* __restrict__ a_src, const float* __restrict__ a_dst,
    float* __restrict__ ssrc, float* __restrict__ sdst) {
    const int BM = 128, BK = 32, TM = 8;
    const int TX = BN / TN;  // 16
    __shared__ float As[BK][BM + 4];  // [k][m]
    __shared__ float Bs[BK][BN];      // [k][c]

    const int tid = threadIdx.x;
    const int tx = tid % TX, ty = tid / TX;
    const int mbase = blockIdx.x * BM, cbase = blockIdx.y * BN;
    const int lane = tid & 31;

    float acc[TM][TN] = {};

    for (int kc = 0; kc < K; kc += BK) {
        // stage A (transposed): BM*BK/4 = 1024 float4; 4 per thread
        #pragma unroll
        for (int r = 0; r < (BM * BK / 4) / 256; r++) {
            int f = tid + r * 256;
            int row = f >> 3, kq = f & 7;
            int gm = mbase + row;
            float4 v = make_float4(0.f, 0.f, 0.f, 0.f);
            if (gm < N_NODES) v = *(const float4*)(A + (size_t)gm * K + kc + kq * 4);
            As[kq * 4 + 0][row] = v.x;
            As[kq * 4 + 1][row] = v.y;
            As[kq * 4 + 2][row] = v.z;
            As[kq * 4 + 3][row] = v.w;
        }
        // stage B direct
        #pragma unroll
        for (int r = 0; r < (BK * BN / 4) / 256; r++) {
            int f = tid + r * 256;
            int c4 = f % (BN / 4), kr = f / (BN / 4);
            *(float4*)&Bs[kr][c4 * 4] =
                *(const float4*)(B + (size_t)(kc + kr) * NC + cbase + c4 * 4);
        }
        __syncthreads();
        #pragma unroll
        for (int k = 0; k < BK; k++) {
            float a[TM], b[TN];
            #pragma unroll
            for (int i = 0; i < TM; i += 4) *(float4*)&a[i] = *(const float4*)&As[k][ty * TM + i];
            #pragma unroll
            for (int j = 0; j < TN; j += 4) *(float4*)&b[j] = *(const float4*)&Bs[k][tx * TN + j];
            #pragma unroll
            for (int i = 0; i < TM; i++)
                #pragma unroll
                for (int j = 0; j < TN; j++) acc[i][j] += a[i] * b[j];
        }
        __syncthreads();
    }

    // store C tile
    #pragma unroll
    for (int i = 0; i < TM; i++) {
        int gm = mbase + ty * TM + i;
        if (gm < N_NODES) {
            #pragma unroll
            for (int j = 0; j < TN; j += 4)
                *(float4*)(C + (size_t)gm * NC + cbase + tx * TN + j) =
                    make_float4(acc[i][j], acc[i][j + 1], acc[i][j + 2], acc[i][j + 3]);
        }
    }

    // fused score epilogue: TPH lanes share one (row, head)
    const int CPH = 64;                 // channels per head
    const int TPH = CPH / TN;           // 8 (BN=128) or 16 (BN=64)
    float av[TN], dv[TN];
    #pragma unroll
    for (int j = 0; j < TN; j++) {
        av[j] = __ldg(a_src + cbase + tx * TN + j);
        dv[j] = __ldg(a_dst + cbase + tx * TN + j);
    }
    const int head = (cbase + tx * TN) / CPH;
    #pragma unroll
    for (int i = 0; i < TM; i++) {
        float ps = 0.f, pd = 0.f;
        #pragma unroll
        for (int j = 0; j < TN; j++) { ps += acc[i][j] * av[j]; pd += acc[i][j] * dv[j]; }
        #pragma unroll
        for (int o = 1; o < TPH; o <<= 1) {
            ps += __shfl_xor_sync(0xFFFFFFFFu, ps, o);
            pd += __shfl_xor_sync(0xFFFFFFFFu, pd, o);
        }
        int gm = mbase + ty * TM + i;
        if ((lane % TPH) == 0 && gm < N_NODES) {
            ssrc[(size_t)gm * H + head] = ps;
            sdst[(size_t)gm * H + head] = pd;
        }
    }
}

// ---------------- ce[h] = dot(We[h*C..], ae[h*C..]) ----------------
template <int H, int C>
__global__ void ce_kernel(const float* __restrict__ We, const float* __restrict__ ae,
                          float* __restrict__ ce) {
    int h = threadIdx.x >> 5;
    int lane = threadIdx.x & 31;
    float s = 0.f;
    for (int c = lane; c < C; c += 32) s += We[h * C + c] * ae[h * C + c];
    #pragma unroll
    for (int off = 16; off > 0; off >>= 1) s += __shfl_xor_sync(0xFFFFFFFFu, s, off);
    if (lane == 0) ce[h] = s;
}

// ---------------- fused softmax + aggregation + bias(+ELU): warp per dst node ----------------
template <int H, int C, bool ELU>
__global__ __launch_bounds__(256) void node_agg(
    const int* __restrict__ off, const int* __restrict__ csrc, const float* __restrict__ cea,
    const float* __restrict__ ssrc, const float* __restrict__ sdst, const float* __restrict__ ce,
    const float* __restrict__ hfeat, const float* __restrict__ bias, float* __restrict__ out) {
    const int F = H * C, PER = F / 32;
    int d = (blockIdx.x * blockDim.x + threadIdx.x) >> 5;
    int lane = threadIdx.x & 31;
    if (d >= N_NODES) return;

    int e0 = off[d], e1 = off[d + 1];

    float sd[H], cv[H];
    #pragma unroll
    for (int h = 0; h < H; h++) { sd[h] = sdst[(size_t)d * H + h]; cv[h] = ce[h]; }

    // phase 1: online softmax (max + denom) over this node's edges
    float m[H], ss[H];
    #pragma unroll
    for (int h = 0; h < H; h++) { m[h] = -1e30f; ss[h] = 0.f; }

    for (int e = e0 + lane; e < e1; e += 32) {
        int s = csrc[e];
        float a = cea[e];
        float sv[H];
        if (H == 4) {
            float4 t = *(const float4*)(ssrc + (size_t)s * 4);
            sv[0] = t.x; sv[1] = t.y; sv[2] = t.z; sv[3] = t.w;
        } else {
            sv[0] = ssrc[s];
        }
        #pragma unroll
        for (int h = 0; h < H; h++) {
            float v = sv[h] + sd[h] + a * cv[h];
            v = (v >= 0.f) ? v : 0.2f * v;
            float nm = fmaxf(m[h], v);
            ss[h] = ss[h] * __expf(m[h] - nm) + __expf(v - nm);
            m[h] = nm;
        }
    }
    #pragma unroll
    for (int o = 16; o > 0; o >>= 1) {
        #pragma unroll
        for (int h = 0; h < H; h++) {
            float m2 = __shfl_xor_sync(0xFFFFFFFFu, m[h], o);
            float s2 = __shfl_xor_sync(0xFFFFFFFFu, ss[h], o);
            float nm = fmaxf(m[h], m2);
            ss[h] = ss[h] * __expf(m[h] - nm) + s2 * __expf(m2 - nm);
            m[h] = nm;
        }
    }

    // select this lane's head constants (compile-time unrolled)
    const int hme = (lane * PER) / C;
    float my_m = m[0], my_s = ss[0], my_sd = sd[0], my_ce = cv[0];
    #pragma unroll
    for (int h = 1; h < H; h++)
        if (hme == h) { my_m = m[h]; my_s = ss[h]; my_sd = sd[h]; my_ce = cv[h]; }
    float inv = 1.f / (my_s + 1e-16f);

    // phase 2: weighted gather-accumulate, 2 edges in flight
    float acc[PER];
    #pragma unroll
    for (int i = 0; i < PER; i++) acc[i] = 0.f;

    int e = e0;
    for (; e + 2 <= e1; e += 2) {
        int s0 = csrc[e], s1 = csrc[e + 1];
        float aa0 = cea[e], aa1 = cea[e + 1];
        float v0 = ssrc[(size_t)s0 * H + hme] + my_sd + aa0 * my_ce;
        float v1 = ssrc[(size_t)s1 * H + hme] + my_sd + aa1 * my_ce;
        v0 = (v0 >= 0.f) ? v0 : 0.2f * v0;
        v1 = (v1 >= 0.f) ? v1 : 0.2f * v1;
        float c0 = __expf(v0 - my_m) * inv;
        float c1 = __expf(v1 - my_m) * inv;
        const float* sp0 = hfeat + (size_t)s0 * F + lane * PER;
        const float* sp1 = hfeat + (size_t)s1 * F + lane * PER;
        if (PER == 8) {
            float4 x0 = *(const float4*)sp0;
            float4 x1 = *(const float4*)(sp0 + 4);
            float4 y0 = *(const float4*)sp1;
            float4 y1 = *(const float4*)(sp1 + 4);
            acc[0] += c0 * x0.x + c1 * y0.x; acc[1] += c0 * x0.y + c1 * y0.y;
            acc[2] += c0 * x0.z + c1 * y0.z; acc[3] += c0 * x0.w + c1 * y0.w;
            acc[4] += c0 * x1.x + c1 * y1.x; acc[5] += c0 * x1.y + c1 * y1.y;
            acc[6] += c0 * x1.z + c1 * y1.z; acc[7] += c0 * x1.w + c1 * y1.w;
        } else {
            float2 x0 = *(const float2*)sp0;
            float2 y0 = *(const float2*)sp1;
            acc[0] += c0 * x0.x + c1 * y0.x;
            acc[1] += c0 * x0.y + c1 * y0.y;
        }
    }
    for (; e < e1; e++) {
        int s = csrc[e];
        float a = cea[e];
        float v = ssrc[(size_t)s * H + hme] + my_sd + a * my_ce;
        v = (v >= 0.f) ? v : 0.2f * v;
        float coef = __expf(v - my_m) * inv;
        const float* sp = hfeat + (size_t)s * F + lane * PER;
        if (PER == 8) {
            float4 v0 = *(const float4*)sp;
            float4 v1 = *(const float4*)(sp + 4);
            acc[0] += coef * v0.x; acc[1] += coef * v0.y;
            acc[2] += coef * v0.z; acc[3] += coef * v0.w;
            acc[4] += coef * v1.x; acc[5] += coef * v1.y;
            acc[6] += coef * v1.z; acc[7] += coef * v1.w;
        } else {
            float2 v0 = *(const float2*)sp;
            acc[0] += coef * v0.x; acc[1] += coef * v0.y;
        }
    }

    // epilogue: bias (+ELU), single plain store
    float* op = out + (size_t)d * F + lane * PER;
    #pragma unroll
    for (int i = 0; i < PER; i++) {
        float v = acc[i] + bias[lane * PER + i];
        if (ELU) v = (v > 0.f) ? v : expm1f(v);
        op[i] = v;
    }
}

// ---------------- launch ----------------
extern "C" void kernel_launch(void* const* d_in, const int* in_sizes, int n_in,
                              void* d_out, int out_size) {
    const float* x   = (const float*)d_in[0];
    const int*   ei  = (const int*)d_in[1];
    const float* ea  = (const float*)d_in[2];
    const float* W1  = (const float*)d_in[3];
    const float* We1 = (const float*)d_in[4];
    const float* as1 = (const float*)d_in[5];
    const float* ad1 = (const float*)d_in[6];
    const float* ae1 = (const float*)d_in[7];
    const float* b1  = (const float*)d_in[8];
    const float* W2  = (const float*)d_in[9];
    const float* We2 = (const float*)d_in[10];
    const float* as2 = (const float*)d_in[11];
    const float* ad2 = (const float*)d_in[12];
    const float* ae2 = (const float*)d_in[13];
    const float* b2  = (const float*)d_in[14];
    float* out = (float*)d_out;

    void* p;
    #define SYM(var, sym) cudaGetSymbolAddress(&p, sym); auto* var = (decltype(&sym[0]))p
    SYM(h1, g_h1);       SYM(out1, g_out1);   SYM(h2, g_h2);
    SYM(ssrc1, g_ssrc1); SYM(sdst1, g_sdst1);
    SYM(ssrc2, g_ssrc2); SYM(sdst2, g_sdst2);
    SYM(asum, g_asum);   SYM(deg, g_deg);
    SYM(part, g_part);   SYM(bsum, g_bsum);   SYM(off, g_off);
    SYM(fill, g_fill);   SYM(csrc, g_csrc);   SYM(cea, g_cea);
    SYM(ce1, g_ce1);     SYM(ce2, g_ce2);
    #undef SYM

    const int NB_E  = (N_EDGES + 255) / 256;
    const int NB_NW = (N_NODES * 32 + 255) / 256;  // warp-per-node kernels
    const int GB_M  = (N_NODES + 127) / 128;       // 391

    // --- CSR build (degree -> scan -> scatter; self-loop at slot 0) ---
    init_pre<<<NBLK_N, 256>>>(deg, asum);
    edge_stats<<<NB_E, 256>>>(ei, ea, deg, asum);
    scan_block<<<NBLK_N, 256>>>(deg, part, bsum);
    scan_tops<<<1, 256>>>(bsum);
    scan_final_selfloop<<<NBLK_N, 256>>>(part, bsum, deg, asum, off, csrc, cea, fill);
    csr_fill<<<NB_E, 256>>>(ei, ea, off, fill, csrc, cea);

    // --- layer 1 ---
    gemm_score_kernel<IN_DIM, F1, 128, 8, HH1>
        <<<dim3(GB_M, F1 / 128), 256>>>(x, W1, h1, as1, ad1, ssrc1, sdst1);
    ce_kernel<HH1, CC1><<<1, 32 * HH1>>>(We1, ae1, ce1);
    node_agg<HH1, CC1, true><<<NB_NW, 256>>>(off, csrc, cea, ssrc1, sdst1, ce1, h1, b1, out1);

    // --- layer 2 ---
    gemm_score_kernel<F1, F2, 64, 4, HH2>
        <<<dim3(GB_M, F2 / 64), 256>>>(out1, W2, h2, as2, ad2, ssrc2, sdst2);
    ce_kernel<HH2, CC2><<<1, 32 * HH2>>>(We2, ae2, ce2);
    node_agg<HH2, CC2, false><<<NB_NW, 256>>>(off, csrc, cea, ssrc2, sdst2, ce2, h2, b2, out);
}